// round 3
// baseline (speedup 1.0000x reference)
#include <cuda_runtime.h>
#include <cstdint>

#define EPSV 1e-5f
#define N4K  4096
#define BROWS 512

// ---------------- scratch (static __device__: allocation-free) ----------------
__device__ float g_M[(size_t)N4K * N4K];        // injected matrix (pre column-norm)
__device__ float g_cw_part[16][N4K];            // partial col sumsq of weight
__device__ float g_cm_part[64][N4K];            // partial col sumsq of M
__device__ float g_invcw[N4K];
__device__ float g_invcmn[N4K];
__device__ float g_invrn[BROWS];
__device__ float g_ql[N4K];

// ---------------- f32x2 helpers ----------------
__device__ __forceinline__ unsigned long long pk2(float v) {
    unsigned long long r;
    asm("mov.b64 %0, {%1, %1};" : "=l"(r) : "f"(v));
    return r;
}
__device__ __forceinline__ unsigned long long fma2(unsigned long long a,
                                                   unsigned long long b,
                                                   unsigned long long c) {
    unsigned long long d;
    asm("fma.rn.f32x2 %0, %1, %2, %3;" : "=l"(d) : "l"(a), "l"(b), "l"(c));
    return d;
}
__device__ __forceinline__ void upk2(unsigned long long v, float& lo, float& hi) {
    asm("mov.b64 {%0, %1}, %2;" : "=f"(lo), "=f"(hi) : "l"(v));
}

// ---------------- K0: ql vector ----------------
__global__ void k_ql(const int* __restrict__ qit, const int* __restrict__ iters) {
    int t = blockIdx.x * 256 + threadIdx.x;
    int it = *iters + 1;
    bool active = (it - qit[t]) <= 200;
    g_ql[t] = ((it > 8000) && active) ? 0.15f : 0.0f;
}

// ---------------- K1: inverse row norms of x ----------------
__global__ void k_rownorm(const float* __restrict__ x) {
    __shared__ float red[256];
    int b = blockIdx.x, t = threadIdx.x;
    const float* row = x + (size_t)b * N4K;
    float s = 0.f;
#pragma unroll
    for (int i = 0; i < 16; i++) { float v = row[t + i * 256]; s += v * v; }
    red[t] = s; __syncthreads();
    for (int o = 128; o > 0; o >>= 1) { if (t < o) red[t] += red[t + o]; __syncthreads(); }
    if (t == 0) g_invrn[b] = 1.0f / fmaxf(sqrtf(red[0]), EPSV);
}

// ---------------- K2: partial column sumsq of weight ----------------
__global__ void k_colsq_w(const float* __restrict__ w) {
    int j = blockIdx.x * 256 + threadIdx.x;
    int s = blockIdx.y;                       // 16 splits of 256 rows
    const float* p = w + (size_t)(s * 256) * N4K + j;
    float acc = 0.f;
#pragma unroll 8
    for (int r = 0; r < 256; r++) { float v = p[(size_t)r * N4K]; acc += v * v; }
    g_cw_part[s][j] = acc;
}

// ---------------- K3: finalize invcw ----------------
__global__ void k_invcw() {
    int j = blockIdx.x * 256 + threadIdx.x;
    float s = 0.f;
#pragma unroll
    for (int p = 0; p < 16; p++) s += g_cw_part[p][j];
    g_invcw[j] = 1.0f / fmaxf(sqrtf(s), EPSV);
}

// ---------------- K4: build M + partial column sumsq of M ----------------
// block = (64,4), tile = 64 i-rows x 64 j-cols. qf needs transposed access ->
// stage a 64x64 qf tile through smem (pad 65 to kill bank conflicts).
__global__ void k_build(const float* __restrict__ w, const float* __restrict__ qf) {
    __shared__ float sq[64][65];
    __shared__ float r2[4][64];
    int tx = threadIdx.x, ty = threadIdx.y;
    int j0 = blockIdx.x * 64, i0 = blockIdx.y * 64;

    for (int jl = ty; jl < 64; jl += 4)
        sq[jl][tx] = qf[(size_t)(j0 + jl) * N4K + i0 + tx];
    __syncthreads();

    int j = j0 + tx;
    float icw = g_invcw[j];
    float acc = 0.f;
#pragma unroll
    for (int il = ty; il < 64; il += 4) {
        int i = i0 + il;
        float q = g_ql[i];
        float m = w[(size_t)i * N4K + j] * icw * (1.0f - q) + sq[tx][il] * q;
        g_M[(size_t)i * N4K + j] = m;
        acc += m * m;
    }
    r2[ty][tx] = acc; __syncthreads();
    if (ty == 0)
        g_cm_part[blockIdx.y][j] = r2[0][tx] + r2[1][tx] + r2[2][tx] + r2[3][tx];
}

// ---------------- K5: finalize invcmn ----------------
__global__ void k_invcmn() {
    int j = blockIdx.x * 256 + threadIdx.x;
    float s = 0.f;
#pragma unroll
    for (int p = 0; p < 64; p++) s += g_cm_part[p][j];
    g_invcmn[j] = 1.0f / fmaxf(sqrtf(s), EPSV);
}

// ---------------- K6: GEMM 512x4096x4096, f32x2 FFMA2 ----------------
// BM=128 BN=128 BK=16, 256 threads, 8x8 per thread (4 packed f32x2 cols).
__global__ __launch_bounds__(256) void k_gemm(const float* __restrict__ A,
                                              float* __restrict__ out) {
    __shared__ __align__(16) float As[16][128];   // transposed A tile
    __shared__ __align__(16) float Bs[16][128];

    int tid = threadIdx.x;
    int tx = tid & 15, ty = tid >> 4;
    int bn0 = blockIdx.x * 128, bm0 = blockIdx.y * 128;

    // global-load mapping
    int arow  = tid >> 2;            // 0..63  (two rows: arow, arow+64)
    int acol4 = (tid & 3) * 4;       // k-offset within tile
    int brow  = tid >> 5;            // 0..7   (two rows: brow, brow+8)
    int bcol4 = (tid & 31) * 4;

    unsigned long long acc[8][4];
#pragma unroll
    for (int r = 0; r < 8; r++)
#pragma unroll
        for (int c = 0; c < 4; c++) acc[r][c] = 0ULL;

    const float* __restrict__ B = g_M;

    float4 pa0, pa1, pb0, pb1;
    {
        pa0 = *(const float4*)&A[(size_t)(bm0 + arow)      * N4K + acol4];
        pa1 = *(const float4*)&A[(size_t)(bm0 + arow + 64) * N4K + acol4];
        pb0 = *(const float4*)&B[(size_t)(brow)     * N4K + bn0 + bcol4];
        pb1 = *(const float4*)&B[(size_t)(brow + 8) * N4K + bn0 + bcol4];
    }

    for (int t = 0; t < 256; t++) {
        // stage prefetched tile into smem (A transposed)
        As[acol4 + 0][arow] = pa0.x;  As[acol4 + 1][arow] = pa0.y;
        As[acol4 + 2][arow] = pa0.z;  As[acol4 + 3][arow] = pa0.w;
        As[acol4 + 0][arow + 64] = pa1.x;  As[acol4 + 1][arow + 64] = pa1.y;
        As[acol4 + 2][arow + 64] = pa1.z;  As[acol4 + 3][arow + 64] = pa1.w;
        *(float4*)&Bs[brow][bcol4]     = pb0;
        *(float4*)&Bs[brow + 8][bcol4] = pb1;
        __syncthreads();

        if (t < 255) {
            int k0 = (t + 1) * 16;
            pa0 = *(const float4*)&A[(size_t)(bm0 + arow)      * N4K + k0 + acol4];
            pa1 = *(const float4*)&A[(size_t)(bm0 + arow + 64) * N4K + k0 + acol4];
            pb0 = *(const float4*)&B[(size_t)(k0 + brow)     * N4K + bn0 + bcol4];
            pb1 = *(const float4*)&B[(size_t)(k0 + brow + 8) * N4K + bn0 + bcol4];
        }

#pragma unroll
        for (int k = 0; k < 16; k++) {
            float4 a0 = *(const float4*)&As[k][ty * 8];
            float4 a1 = *(const float4*)&As[k][ty * 8 + 4];
            ulonglong2 bA = *(const ulonglong2*)&Bs[k][tx * 8];
            ulonglong2 bB = *(const ulonglong2*)&Bs[k][tx * 8 + 4];
            unsigned long long ad[8] = {pk2(a0.x), pk2(a0.y), pk2(a0.z), pk2(a0.w),
                                        pk2(a1.x), pk2(a1.y), pk2(a1.z), pk2(a1.w)};
#pragma unroll
            for (int r = 0; r < 8; r++) {
                acc[r][0] = fma2(ad[r], bA.x, acc[r][0]);
                acc[r][1] = fma2(ad[r], bA.y, acc[r][1]);
                acc[r][2] = fma2(ad[r], bB.x, acc[r][2]);
                acc[r][3] = fma2(ad[r], bB.y, acc[r][3]);
            }
        }
        __syncthreads();
    }

    // epilogue: fold row + column normalizations
    float cs[8];
#pragma unroll
    for (int c = 0; c < 8; c++) cs[c] = g_invcmn[bn0 + tx * 8 + c];
#pragma unroll
    for (int r = 0; r < 8; r++) {
        int row = bm0 + ty * 8 + r;
        float ir = g_invrn[row];
        float o[8];
#pragma unroll
        for (int c2 = 0; c2 < 4; c2++) {
            float lo, hi;
            upk2(acc[r][c2], lo, hi);
            o[2 * c2]     = lo * ir * cs[2 * c2];
            o[2 * c2 + 1] = hi * ir * cs[2 * c2 + 1];
        }
        float4* po = (float4*)&out[(size_t)row * N4K + bn0 + tx * 8];
        po[0] = make_float4(o[0], o[1], o[2], o[3]);
        po[1] = make_float4(o[4], o[5], o[6], o[7]);
    }
}

// ---------------- launch ----------------
extern "C" void kernel_launch(void* const* d_in, const int* in_sizes, int n_in,
                              void* d_out, int out_size) {
    const float* x   = (const float*)d_in[0];   // (512, 4096)
    const float* w   = (const float*)d_in[1];   // (4096, 4096)
    const float* qf  = (const float*)d_in[2];   // (4096, 4096)
    const int*   qit = (const int*)d_in[3];     // (4096,)
    const int*   it  = (const int*)d_in[4];     // scalar
    float* out = (float*)d_out;                 // (512, 4096) fp32

    k_ql<<<16, 256>>>(qit, it);
    k_rownorm<<<BROWS, 256>>>(x);
    k_colsq_w<<<dim3(16, 16), 256>>>(w);
    k_invcw<<<16, 256>>>();
    k_build<<<dim3(64, 64), dim3(64, 4)>>>(w, qf);
    k_invcmn<<<16, 256>>>();
    k_gemm<<<dim3(32, 4), 256>>>(x, out);
}

// round 5
// speedup vs baseline: 2.1312x; 2.1312x over previous
#include <cuda_runtime.h>
#include <cstdint>

#define EPSV 1e-5f
#define N4K  4096
#define BROWS 512

// ---------------- scratch (static __device__: allocation-free) ----------------
__device__ float g_Mt[(size_t)N4K * N4K];     // injected matrix, TRANSPOSED: [j][i], tf32-rounded
__device__ float g_cw_part[16][N4K];          // partial col sumsq of weight
__device__ float g_invcw[N4K];
__device__ float g_invcmn[N4K];
__device__ float g_invrn[BROWS];
__device__ float g_ql[N4K];

// ---------------- small helpers ----------------
__device__ __forceinline__ float tf32r(float v) {
    float r;
    asm("cvt.rna.tf32.f32 %0, %1;" : "=f"(r) : "f"(v));
    return r;
}
__device__ __forceinline__ uint32_t s2u(const void* p) {
    uint32_t a;
    asm("{ .reg .u64 t; cvta.to.shared.u64 t, %1; cvt.u32.u64 %0, t; }" : "=r"(a) : "l"(p));
    return a;
}
__device__ __forceinline__ void ldsm4(uint32_t& r0, uint32_t& r1, uint32_t& r2,
                                      uint32_t& r3, uint32_t addr) {
    asm volatile("ldmatrix.sync.aligned.m8n8.x4.shared.b16 {%0,%1,%2,%3}, [%4];"
                 : "=r"(r0), "=r"(r1), "=r"(r2), "=r"(r3) : "r"(addr));
}
__device__ __forceinline__ void mma_tf32(float& d0, float& d1, float& d2, float& d3,
                                         uint32_t a0, uint32_t a1, uint32_t a2, uint32_t a3,
                                         uint32_t b0, uint32_t b1) {
    asm volatile(
        "mma.sync.aligned.m16n8k8.row.col.f32.tf32.tf32.f32 "
        "{%0,%1,%2,%3}, {%4,%5,%6,%7}, {%8,%9}, {%0,%1,%2,%3};"
        : "+f"(d0), "+f"(d1), "+f"(d2), "+f"(d3)
        : "r"(a0), "r"(a1), "r"(a2), "r"(a3), "r"(b0), "r"(b1));
}

// ---------------- K0: ql vector ----------------
__global__ void k_ql(const int* __restrict__ qit, const int* __restrict__ iters) {
    int t = blockIdx.x * 256 + threadIdx.x;
    int it = *iters + 1;
    bool active = (it - qit[t]) <= 200;
    g_ql[t] = ((it > 8000) && active) ? 0.15f : 0.0f;
}

// ---------------- K1: inverse row norms of x (warp per row) ----------------
__global__ void k_rownorm(const float* __restrict__ x) {
    int w = threadIdx.x >> 5, lid = threadIdx.x & 31;
    int b = blockIdx.x * 8 + w;
    const float4* p = (const float4*)(x + (size_t)b * N4K);
    float s = 0.f;
#pragma unroll
    for (int i = 0; i < 32; i++) {
        float4 v = p[lid + i * 32];
        s += v.x * v.x + v.y * v.y + v.z * v.z + v.w * v.w;
    }
#pragma unroll
    for (int o = 16; o; o >>= 1) s += __shfl_xor_sync(0xFFFFFFFFu, s, o);
    if (lid == 0) g_invrn[b] = 1.0f / fmaxf(sqrtf(s), EPSV);
}

// ---------------- K2: partial column sumsq of weight ----------------
__global__ void k_colsq_w(const float* __restrict__ w) {
    int j = blockIdx.x * 256 + threadIdx.x;
    int s = blockIdx.y;                       // 16 splits of 256 rows
    const float* p = w + (size_t)(s * 256) * N4K + j;
    float acc = 0.f;
#pragma unroll 8
    for (int r = 0; r < 256; r++) { float v = p[(size_t)r * N4K]; acc += v * v; }
    g_cw_part[s][j] = acc;
}

// ---------------- K3: finalize invcw ----------------
__global__ void k_invcw() {
    int j = blockIdx.x * 256 + threadIdx.x;
    float s = 0.f;
#pragma unroll
    for (int p = 0; p < 16; p++) s += g_cw_part[p][j];
    g_invcw[j] = 1.0f / fmaxf(sqrtf(s), EPSV);
}

// ---------------- K4: build Mt[j][i] (transposed, tf32-rounded) ----------------
// Mt[j][i] = w[i][j]*invcw[j]*(1-ql[i]) + qf[j][i]*ql[i]
__global__ void k_build(const float* __restrict__ w, const float* __restrict__ qf) {
    __shared__ float swt[64][65];
    int tx = threadIdx.x, ty = threadIdx.y;
    int i0 = blockIdx.x * 64, j0 = blockIdx.y * 64;

    for (int il = ty; il < 64; il += 4)
        swt[il][tx] = w[(size_t)(i0 + il) * N4K + j0 + tx];   // coalesced over j
    __syncthreads();

    float q = g_ql[i0 + tx];
    float oq = 1.0f - q;
#pragma unroll
    for (int jl = ty; jl < 64; jl += 4) {
        int j = j0 + jl;
        float icw = g_invcw[j];
        float m = swt[tx][jl] * icw * oq + qf[(size_t)j * N4K + i0 + tx] * q;
        g_Mt[(size_t)j * N4K + i0 + tx] = tf32r(m);
    }
}

// ---------------- K5: invcmn = inverse row norms of Mt (warp per row) ----------------
__global__ void k_rowsq_mt() {
    int w = threadIdx.x >> 5, lid = threadIdx.x & 31;
    int j = blockIdx.x * 8 + w;
    const float4* p = (const float4*)(g_Mt + (size_t)j * N4K);
    float s = 0.f;
#pragma unroll
    for (int i = 0; i < 32; i++) {
        float4 v = p[lid + i * 32];
        s += v.x * v.x + v.y * v.y + v.z * v.z + v.w * v.w;
    }
#pragma unroll
    for (int o = 16; o; o >>= 1) s += __shfl_xor_sync(0xFFFFFFFFu, s, o);
    if (lid == 0) g_invcmn[j] = 1.0f / fmaxf(sqrtf(s), EPSV);
}

// ---------------- K6: tf32 mma.sync GEMM ----------------
// out[512,4096] = x @ Mt^T, norms folded in epilogue.
// BM=128, BN=128, BK=32; 8 warps (2 m x 4 n), warp tile 64x32, m16n8k8 HMMA.
// Both operands K-major in smem (SW128-style swizzle); ldmatrix.x4.b16 gives
// exact tf32 fragments for A (row) and B (col, since Mt is [n][k]).
#define SWZ(o) ((o) ^ (((o) >> 3) & 0x70))
static constexpr int SMEM_DYN = 1024 + 65536;

__global__ __launch_bounds__(256, 1)
void k_gemm_mma(const float* __restrict__ A, float* __restrict__ out) {
    extern __shared__ char smraw[];
    uint32_t raw = s2u(smraw);
    uint32_t sb = (raw + 1023) & ~1023u;       // 1024-aligned tile base
    char* smp = smraw + (sb - raw);
    // layout: A stage0 @0, A stage1 @16384, B stage0 @32768, B stage1 @49152

    int tid = threadIdx.x;
    int lane = tid & 31, wid = tid >> 5;
    int wm = (wid >> 2) * 64;                  // warp m offset (0,64)
    int wn = (wid & 3) * 32;                   // warp n offset (0..96)
    int bn0 = blockIdx.x * 128, bm0 = blockIdx.y * 128;

    const float* __restrict__ B = g_Mt;

    // ldmatrix per-lane addressing
    int q = lane >> 3, rr = lane & 7;
    int qk = (q >> 1) * 16;                    // 16B k-offset for high-k quads
    uint32_t xr = (uint32_t)(rr << 4);         // swizzle XOR (row%8)<<4
    int aRowL = wm + (q & 1) * 8 + rr;         // A row for matrix pair
    int bRowL = wn + (q & 1) * 8 + rr;         // B row (n) for matrix pair

    float acc[4][4][4];
#pragma unroll
    for (int mt = 0; mt < 4; mt++)
#pragma unroll
        for (int n8 = 0; n8 < 4; n8++)
#pragma unroll
            for (int c = 0; c < 4; c++) acc[mt][n8][c] = 0.f;

    float4 pa[4], pb[4];
#define LDTILE(k0)                                                              \
    {                                                                           \
        _Pragma("unroll")                                                       \
        for (int i = 0; i < 4; i++) {                                           \
            int fid = tid + 256 * i;                                            \
            int r = fid >> 3, g = fid & 7;                                      \
            pa[i] = *(const float4*)&A[(size_t)(bm0 + r) * N4K + (k0) + g * 4]; \
            pb[i] = *(const float4*)&B[(size_t)(bn0 + r) * N4K + (k0) + g * 4]; \
        }                                                                       \
    }

    LDTILE(0);

    for (int t = 0; t < 128; t++) {
        int s = t & 1;
        uint32_t aOff = (uint32_t)s * 16384;
        uint32_t bOff = 32768u + (uint32_t)s * 16384;
        // ---- stage registers -> smem (A converted to tf32) ----
#pragma unroll
        for (int i = 0; i < 4; i++) {
            int fid = tid + 256 * i;
            int r = fid >> 3, g = fid & 7;
            uint32_t off = (uint32_t)(r * 128 + g * 16);
            uint32_t sw = SWZ(off);
            *(float4*)(smp + aOff + sw) = make_float4(tf32r(pa[i].x), tf32r(pa[i].y),
                                                      tf32r(pa[i].z), tf32r(pa[i].w));
            *(float4*)(smp + bOff + sw) = pb[i];
        }
        __syncthreads();
        if (t < 127) LDTILE((t + 1) * 32);

        // ---- compute: 4 k-steps of 8 ----
#pragma unroll
        for (int ks = 0; ks < 4; ks++) {
            uint32_t kb = (uint32_t)((ks * 32 + qk)) ^ xr;
            uint32_t a[4][4], b[2][4];
#pragma unroll
            for (int mt = 0; mt < 4; mt++)
                ldsm4(a[mt][0], a[mt][1], a[mt][2], a[mt][3],
                      sb + aOff + (uint32_t)(aRowL + mt * 16) * 128 + kb);
#pragma unroll
            for (int nt = 0; nt < 2; nt++)
                ldsm4(b[nt][0], b[nt][1], b[nt][2], b[nt][3],
                      sb + bOff + (uint32_t)(bRowL + nt * 16) * 128 + kb);
#pragma unroll
            for (int mt = 0; mt < 4; mt++)
#pragma unroll
                for (int n8 = 0; n8 < 4; n8++)
                    mma_tf32(acc[mt][n8][0], acc[mt][n8][1], acc[mt][n8][2], acc[mt][n8][3],
                             a[mt][0], a[mt][1], a[mt][2], a[mt][3],
                             b[n8 >> 1][n8 & 1], b[n8 >> 1][(n8 & 1) + 2]);
        }
        __syncthreads();
    }

    // ---- epilogue: fold row + column norms, write fp32 ----
    int g4 = lane >> 2, t4 = lane & 3;
#pragma unroll
    for (int mt = 0; mt < 4; mt++) {
        int row0 = bm0 + wm + mt * 16 + g4;
        int row1 = row0 + 8;
        float ir0 = g_invrn[row0], ir1 = g_invrn[row1];
#pragma unroll
        for (int n8 = 0; n8 < 4; n8++) {
            int col = bn0 + wn + n8 * 8 + 2 * t4;
            float c0 = g_invcmn[col], c1 = g_invcmn[col + 1];
            float2 v0 = make_float2(acc[mt][n8][0] * ir0 * c0, acc[mt][n8][1] * ir0 * c1);
            float2 v1 = make_float2(acc[mt][n8][2] * ir1 * c0, acc[mt][n8][3] * ir1 * c1);
            *(float2*)&out[(size_t)row0 * N4K + col] = v0;
            *(float2*)&out[(size_t)row1 * N4K + col] = v1;
        }
    }
}

// ---------------- launch ----------------
extern "C" void kernel_launch(void* const* d_in, const int* in_sizes, int n_in,
                              void* d_out, int out_size) {
    const float* x   = (const float*)d_in[0];   // (512, 4096)
    const float* w   = (const float*)d_in[1];   // (4096, 4096)
    const float* qf  = (const float*)d_in[2];   // (4096, 4096)
    const int*   qit = (const int*)d_in[3];     // (4096,)
    const int*   it  = (const int*)d_in[4];     // scalar
    float* out = (float*)d_out;                 // (512, 4096) fp32

    cudaFuncSetAttribute(k_gemm_mma, cudaFuncAttributeMaxDynamicSharedMemorySize, SMEM_DYN);

    k_ql<<<16, 256>>>(qit, it);
    k_rownorm<<<64, 256>>>(x);
    k_colsq_w<<<dim3(16, 16), 256>>>(w);
    k_invcw<<<16, 256>>>();
    k_build<<<dim3(64, 64), dim3(64, 4)>>>(w, qf);
    k_rowsq_mt<<<512, 256>>>();
    k_gemm_mma<<<dim3(32, 4), 256, SMEM_DYN>>>(x, out);
}

// round 6
// speedup vs baseline: 3.2168x; 1.5094x over previous
#include <cuda_runtime.h>
#include <cuda_fp16.h>
#include <cstdint>

#define EPSV 1e-5f
#define N4K  4096
#define BROWS 512

// ---------------- scratch (static __device__: allocation-free) ----------------
__device__ __half g_Mth[(size_t)N4K * N4K];   // injected matrix, TRANSPOSED [j][i], fp16
__device__ __half g_Ah[(size_t)BROWS * N4K];  // x rounded to fp16
__device__ float g_cw_part[16][N4K];          // partial col sumsq of weight
__device__ float g_invcmn[N4K];
__device__ float g_invrn[BROWS];
__device__ float g_ql[N4K];

// ---------------- helpers ----------------
__device__ __forceinline__ uint32_t s2u(const void* p) {
    uint32_t a;
    asm("{ .reg .u64 t; cvta.to.shared.u64 t, %1; cvt.u32.u64 %0, t; }" : "=r"(a) : "l"(p));
    return a;
}
__device__ __forceinline__ void ldsm4(uint32_t& r0, uint32_t& r1, uint32_t& r2,
                                      uint32_t& r3, uint32_t addr) {
    asm volatile("ldmatrix.sync.aligned.m8n8.x4.shared.b16 {%0,%1,%2,%3}, [%4];"
                 : "=r"(r0), "=r"(r1), "=r"(r2), "=r"(r3) : "r"(addr));
}
__device__ __forceinline__ void mma_f16(float& d0, float& d1, float& d2, float& d3,
                                        uint32_t a0, uint32_t a1, uint32_t a2, uint32_t a3,
                                        uint32_t b0, uint32_t b1) {
    asm volatile(
        "mma.sync.aligned.m16n8k16.row.col.f32.f16.f16.f32 "
        "{%0,%1,%2,%3}, {%4,%5,%6,%7}, {%8,%9}, {%0,%1,%2,%3};"
        : "+f"(d0), "+f"(d1), "+f"(d2), "+f"(d3)
        : "r"(a0), "r"(a1), "r"(a2), "r"(a3), "r"(b0), "r"(b1));
}
__device__ __forceinline__ void cpasync16(uint32_t dst, const void* src) {
    asm volatile("cp.async.cg.shared.global [%0], [%1], 16;" :: "r"(dst), "l"(src) : "memory");
}
#define SWZ(o) ((o) ^ (((o) >> 3) & 0x70))

// ---------------- K1: inverse row norms of x + fp16 convert (warp per row) ----------------
__global__ void k_rownorm_xh(const float* __restrict__ x) {
    int w = threadIdx.x >> 5, lid = threadIdx.x & 31;
    int b = blockIdx.x * 8 + w;
    const float4* p = (const float4*)(x + (size_t)b * N4K);
    __half* hrow = g_Ah + (size_t)b * N4K;
    float s = 0.f;
#pragma unroll
    for (int i = 0; i < 32; i++) {
        float4 v = p[lid + i * 32];
        s += v.x * v.x + v.y * v.y + v.z * v.z + v.w * v.w;
        __half2 h0 = __floats2half2_rn(v.x, v.y);
        __half2 h1 = __floats2half2_rn(v.z, v.w);
        uint2 u;
        u.x = *(uint32_t*)&h0; u.y = *(uint32_t*)&h1;
        *(uint2*)&hrow[(size_t)(lid + i * 32) * 4] = u;
    }
#pragma unroll
    for (int o = 16; o; o >>= 1) s += __shfl_xor_sync(0xFFFFFFFFu, s, o);
    if (lid == 0) g_invrn[b] = 1.0f / fmaxf(sqrtf(s), EPSV);
}

// ---------------- K2: partial column sumsq of weight + ql ----------------
__global__ void k_colsq_ql(const float* __restrict__ w, const int* __restrict__ qit,
                           const int* __restrict__ iters) {
    int j = blockIdx.x * 256 + threadIdx.x;
    int s = blockIdx.y;                       // 16 splits of 256 rows
    if (s == 0) {
        int it = *iters + 1;
        bool active = (it - qit[j]) <= 200;
        g_ql[j] = ((it > 8000) && active) ? 0.15f : 0.0f;
    }
    const float* p = w + (size_t)(s * 256) * N4K + j;
    float acc = 0.f;
#pragma unroll 8
    for (int r = 0; r < 256; r++) { float v = p[(size_t)r * N4K]; acc += v * v; }
    g_cw_part[s][j] = acc;
}

// ---------------- K3: build Mth[j][i] fp16 (invcw computed inline) ----------------
// Mth[j][i] = half( w[i][j]*invcw[j]*(1-ql[i]) + qf[j][i]*ql[i] )
__global__ void k_build(const float* __restrict__ w, const float* __restrict__ qf) {
    __shared__ float swt[64][65];
    __shared__ float sicw[64];
    int tx = threadIdx.x, ty = threadIdx.y;
    int i0 = blockIdx.x * 64, j0 = blockIdx.y * 64;

    if (ty == 0) {
        float s = 0.f;
#pragma unroll
        for (int p = 0; p < 16; p++) s += g_cw_part[p][j0 + tx];
        sicw[tx] = 1.0f / fmaxf(sqrtf(s), EPSV);
    }
    for (int il = ty; il < 64; il += 4)
        swt[il][tx] = w[(size_t)(i0 + il) * N4K + j0 + tx];   // coalesced over j
    __syncthreads();

    float q = g_ql[i0 + tx];
    float oq = 1.0f - q;
#pragma unroll
    for (int jl = ty; jl < 64; jl += 4) {
        int j = j0 + jl;
        float m = swt[tx][jl] * sicw[jl] * oq + qf[(size_t)j * N4K + i0 + tx] * q;
        g_Mth[(size_t)j * N4K + i0 + tx] = __float2half_rn(m);
    }
}

// ---------------- K4: invcmn = inverse row norms of Mth (warp per row) ----------------
__global__ void k_rowsq_mt() {
    int w = threadIdx.x >> 5, lid = threadIdx.x & 31;
    int j = blockIdx.x * 8 + w;
    const uint4* p = (const uint4*)(g_Mth + (size_t)j * N4K);   // 8 halfs per uint4
    float s = 0.f;
#pragma unroll
    for (int i = 0; i < 16; i++) {
        uint4 v = p[lid + i * 32];
        float2 f0 = __half22float2(*(__half2*)&v.x);
        float2 f1 = __half22float2(*(__half2*)&v.y);
        float2 f2 = __half22float2(*(__half2*)&v.z);
        float2 f3 = __half22float2(*(__half2*)&v.w);
        s += f0.x * f0.x + f0.y * f0.y + f1.x * f1.x + f1.y * f1.y;
        s += f2.x * f2.x + f2.y * f2.y + f3.x * f3.x + f3.y * f3.y;
    }
#pragma unroll
    for (int o = 16; o; o >>= 1) s += __shfl_xor_sync(0xFFFFFFFFu, s, o);
    if (lid == 0) g_invcmn[j] = 1.0f / fmaxf(sqrtf(s), EPSV);
}

// ---------------- K5: fp16 mma.sync GEMM ----------------
// out[512,4096] = x_h @ Mth^T, norms folded in epilogue.
// BM=128, BN=128, BK=64 halfs; 8 warps (2m x 4n), warp tile 64x32, m16n8k16.
// 4-stage cp.async pipeline, 32KB/stage.
static constexpr int SMEM_DYN = 1024 + 4 * 32768;
static constexpr int NKT = 64;                 // k-tiles of 64

__global__ __launch_bounds__(256, 1)
void k_gemm_mma(float* __restrict__ out) {
    extern __shared__ char smraw[];
    uint32_t raw = s2u(smraw);
    uint32_t sb = (raw + 1023) & ~1023u;       // 1024-aligned base
    // stage st: A at sb + st*32768 (16KB), B at +16384

    int tid = threadIdx.x;
    int lane = tid & 31, wid = tid >> 5;
    int wm = (wid >> 2) * 64;                  // warp m offset (0,64)
    int wn = (wid & 3) * 32;                   // warp n offset (0..96)
    int bn0 = blockIdx.x * 128, bm0 = blockIdx.y * 128;

    // ldmatrix per-lane addressing
    int q = lane >> 3, rr = lane & 7;
    uint32_t qk = (uint32_t)(q >> 1) * 16;     // +16B for high-k quads
    uint32_t xr = (uint32_t)(rr << 4);         // swizzle XOR
    int aRowL = wm + (q & 1) * 8 + rr;
    int bRowL = wn + (q & 1) * 8 + rr;

    float acc[4][4][4];
#pragma unroll
    for (int mt = 0; mt < 4; mt++)
#pragma unroll
        for (int n8 = 0; n8 < 4; n8++)
#pragma unroll
            for (int c = 0; c < 4; c++) acc[mt][n8][c] = 0.f;

    // per-thread load mapping: 4 chunks A + 4 chunks B, 16B each
    int lr = tid >> 1;                          // base row pair
    // simpler: fid = tid + 256*i, r = fid>>3 (0..127), c = fid&7 (0..7)
#define LOADSTAGE(st, t)                                                          \
    {                                                                             \
        size_t k0 = (size_t)(t) * 64;                                             \
        uint32_t sa = sb + (uint32_t)(st) * 32768u;                               \
        _Pragma("unroll")                                                         \
        for (int i = 0; i < 4; i++) {                                             \
            int fid = tid + 256 * i;                                              \
            int r = fid >> 3, c = fid & 7;                                        \
            uint32_t so = SWZ((uint32_t)(r * 128 + c * 16));                      \
            cpasync16(sa + so, &g_Ah[(size_t)(bm0 + r) * N4K + k0 + c * 8]);      \
            cpasync16(sa + 16384u + so,                                           \
                      &g_Mth[(size_t)(bn0 + r) * N4K + k0 + c * 8]);              \
        }                                                                         \
    }
#define COMMIT() asm volatile("cp.async.commit_group;" ::: "memory")

    LOADSTAGE(0, 0); COMMIT();
    LOADSTAGE(1, 1); COMMIT();
    LOADSTAGE(2, 2); COMMIT();

    (void)lr;
    for (int t = 0; t < NKT; t++) {
        asm volatile("cp.async.wait_group 2;" ::: "memory");
        __syncthreads();
        if (t + 3 < NKT) { LOADSTAGE((t + 3) & 3, t + 3); }
        COMMIT();

        uint32_t sa = sb + (uint32_t)(t & 3) * 32768u;
        uint32_t sB = sa + 16384u;
#pragma unroll
        for (int ks = 0; ks < 4; ks++) {
            uint32_t kb = ((uint32_t)(ks * 32) + qk) ^ xr;
            uint32_t a[4][4], b[2][4];
#pragma unroll
            for (int mt = 0; mt < 4; mt++)
                ldsm4(a[mt][0], a[mt][1], a[mt][2], a[mt][3],
                      sa + (uint32_t)(aRowL + mt * 16) * 128 + kb);
#pragma unroll
            for (int nt = 0; nt < 2; nt++)
                ldsm4(b[nt][0], b[nt][1], b[nt][2], b[nt][3],
                      sB + (uint32_t)(bRowL + nt * 16) * 128 + kb);
#pragma unroll
            for (int mt = 0; mt < 4; mt++)
#pragma unroll
                for (int n8 = 0; n8 < 4; n8++)
                    mma_f16(acc[mt][n8][0], acc[mt][n8][1], acc[mt][n8][2], acc[mt][n8][3],
                            a[mt][0], a[mt][1], a[mt][2], a[mt][3],
                            b[n8 >> 1][n8 & 1], b[n8 >> 1][(n8 & 1) + 2]);
        }
    }

    // ---- epilogue: fold row + column norms, write fp32 ----
    int g4 = lane >> 2, t4 = lane & 3;
#pragma unroll
    for (int mt = 0; mt < 4; mt++) {
        int row0 = bm0 + wm + mt * 16 + g4;
        int row1 = row0 + 8;
        float ir0 = g_invrn[row0], ir1 = g_invrn[row1];
#pragma unroll
        for (int n8 = 0; n8 < 4; n8++) {
            int col = bn0 + wn + n8 * 8 + 2 * t4;
            float c0 = g_invcmn[col], c1 = g_invcmn[col + 1];
            float2 v0 = make_float2(acc[mt][n8][0] * ir0 * c0, acc[mt][n8][1] * ir0 * c1);
            float2 v1 = make_float2(acc[mt][n8][2] * ir1 * c0, acc[mt][n8][3] * ir1 * c1);
            *(float2*)&out[(size_t)row0 * N4K + col] = v0;
            *(float2*)&out[(size_t)row1 * N4K + col] = v1;
        }
    }
}

// ---------------- launch ----------------
extern "C" void kernel_launch(void* const* d_in, const int* in_sizes, int n_in,
                              void* d_out, int out_size) {
    const float* x   = (const float*)d_in[0];   // (512, 4096)
    const float* w   = (const float*)d_in[1];   // (4096, 4096)
    const float* qf  = (const float*)d_in[2];   // (4096, 4096)
    const int*   qit = (const int*)d_in[3];     // (4096,)
    const int*   it  = (const int*)d_in[4];     // scalar
    float* out = (float*)d_out;                 // (512, 4096) fp32

    cudaFuncSetAttribute(k_gemm_mma, cudaFuncAttributeMaxDynamicSharedMemorySize, SMEM_DYN);

    k_rownorm_xh<<<64, 256>>>(x);
    k_colsq_ql<<<dim3(16, 16), 256>>>(w, qit, it);
    k_build<<<dim3(64, 64), dim3(64, 4)>>>(w, qf);
    k_rowsq_mt<<<512, 256>>>();
    k_gemm_mma<<<dim3(32, 4), 256, SMEM_DYN>>>(out);
}

// round 7
// speedup vs baseline: 3.2308x; 1.0044x over previous
#include <cuda_runtime.h>
#include <cuda_fp16.h>
#include <cstdint>

#define EPSV 1e-5f
#define N4K  4096
#define BROWS 512

// ---------------- scratch (static __device__: allocation-free) ----------------
__device__ __half g_Mth[(size_t)N4K * N4K];   // injected matrix, TRANSPOSED [j][i], fp16
__device__ __half g_Ah[(size_t)BROWS * N4K];  // x rounded to fp16
__device__ float g_cw_part[16][N4K];          // partial col sumsq of weight
__device__ float g_invcmn[N4K];
__device__ float g_invrn[BROWS];
__device__ float g_ql[N4K];

// ---------------- helpers ----------------
__device__ __forceinline__ uint32_t s2u(const void* p) {
    uint32_t a;
    asm("{ .reg .u64 t; cvta.to.shared.u64 t, %1; cvt.u32.u64 %0, t; }" : "=r"(a) : "l"(p));
    return a;
}
__device__ __forceinline__ void ldsm4(uint32_t& r0, uint32_t& r1, uint32_t& r2,
                                      uint32_t& r3, uint32_t addr) {
    asm volatile("ldmatrix.sync.aligned.m8n8.x4.shared.b16 {%0,%1,%2,%3}, [%4];"
                 : "=r"(r0), "=r"(r1), "=r"(r2), "=r"(r3) : "r"(addr));
}
__device__ __forceinline__ void mma_f16(float& d0, float& d1, float& d2, float& d3,
                                        uint32_t a0, uint32_t a1, uint32_t a2, uint32_t a3,
                                        uint32_t b0, uint32_t b1) {
    asm volatile(
        "mma.sync.aligned.m16n8k16.row.col.f32.f16.f16.f32 "
        "{%0,%1,%2,%3}, {%4,%5,%6,%7}, {%8,%9}, {%0,%1,%2,%3};"
        : "+f"(d0), "+f"(d1), "+f"(d2), "+f"(d3)
        : "r"(a0), "r"(a1), "r"(a2), "r"(a3), "r"(b0), "r"(b1));
}
__device__ __forceinline__ void cpasync16(uint32_t dst, const void* src) {
    asm volatile("cp.async.cg.shared.global [%0], [%1], 16;" :: "r"(dst), "l"(src) : "memory");
}
#define SWZ(o) ((o) ^ (((o) >> 3) & 0x70))

// ---------------- K1: inverse row norms of x + fp16 convert (warp per row) ----------------
__global__ void k_rownorm_xh(const float* __restrict__ x) {
    int w = threadIdx.x >> 5, lid = threadIdx.x & 31;
    int b = blockIdx.x * 8 + w;
    const float4* p = (const float4*)(x + (size_t)b * N4K);
    __half* hrow = g_Ah + (size_t)b * N4K;
    float s = 0.f;
#pragma unroll
    for (int i = 0; i < 32; i++) {
        float4 v = p[lid + i * 32];
        s += v.x * v.x + v.y * v.y + v.z * v.z + v.w * v.w;
        __half2 h0 = __floats2half2_rn(v.x, v.y);
        __half2 h1 = __floats2half2_rn(v.z, v.w);
        uint2 u;
        u.x = *(uint32_t*)&h0; u.y = *(uint32_t*)&h1;
        *(uint2*)&hrow[(size_t)(lid + i * 32) * 4] = u;
    }
#pragma unroll
    for (int o = 16; o; o >>= 1) s += __shfl_xor_sync(0xFFFFFFFFu, s, o);
    if (lid == 0) g_invrn[b] = 1.0f / fmaxf(sqrtf(s), EPSV);
}

// ---------------- K2: partial column sumsq of weight + ql ----------------
__global__ void k_colsq_ql(const float* __restrict__ w, const int* __restrict__ qit,
                           const int* __restrict__ iters) {
    int j = blockIdx.x * 256 + threadIdx.x;
    int s = blockIdx.y;                       // 16 splits of 256 rows
    if (s == 0) {
        int it = *iters + 1;
        bool active = (it - qit[j]) <= 200;
        g_ql[j] = ((it > 8000) && active) ? 0.15f : 0.0f;
    }
    const float* p = w + (size_t)(s * 256) * N4K + j;
    float acc = 0.f;
#pragma unroll 8
    for (int r = 0; r < 256; r++) { float v = p[(size_t)r * N4K]; acc += v * v; }
    g_cw_part[s][j] = acc;
}

// ---------------- K3: build Mth[j][i] fp16 (invcw computed inline) ----------------
// Mth[j][i] = half( w[i][j]*invcw[j]*(1-ql[i]) + qf[j][i]*ql[i] )
__global__ void k_build(const float* __restrict__ w, const float* __restrict__ qf) {
    __shared__ float swt[64][65];
    __shared__ float sicw[64];
    int tx = threadIdx.x, ty = threadIdx.y;
    int i0 = blockIdx.x * 64, j0 = blockIdx.y * 64;

    if (ty == 0) {
        float s = 0.f;
#pragma unroll
        for (int p = 0; p < 16; p++) s += g_cw_part[p][j0 + tx];
        sicw[tx] = 1.0f / fmaxf(sqrtf(s), EPSV);
    }
    for (int il = ty; il < 64; il += 4)
        swt[il][tx] = w[(size_t)(i0 + il) * N4K + j0 + tx];   // coalesced over j
    __syncthreads();

    float q = g_ql[i0 + tx];
    float oq = 1.0f - q;
#pragma unroll
    for (int jl = ty; jl < 64; jl += 4) {
        int j = j0 + jl;
        float m = swt[tx][jl] * sicw[jl] * oq + qf[(size_t)j * N4K + i0 + tx] * q;
        g_Mth[(size_t)j * N4K + i0 + tx] = __float2half_rn(m);
    }
}

// ---------------- K4: invcmn = inverse row norms of Mth (warp per row) ----------------
__global__ void k_rowsq_mt() {
    int w = threadIdx.x >> 5, lid = threadIdx.x & 31;
    int j = blockIdx.x * 8 + w;
    const uint4* p = (const uint4*)(g_Mth + (size_t)j * N4K);   // 8 halfs per uint4
    float s = 0.f;
#pragma unroll
    for (int i = 0; i < 16; i++) {
        uint4 v = p[lid + i * 32];
        float2 f0 = __half22float2(*(__half2*)&v.x);
        float2 f1 = __half22float2(*(__half2*)&v.y);
        float2 f2 = __half22float2(*(__half2*)&v.z);
        float2 f3 = __half22float2(*(__half2*)&v.w);
        s += f0.x * f0.x + f0.y * f0.y + f1.x * f1.x + f1.y * f1.y;
        s += f2.x * f2.x + f2.y * f2.y + f3.x * f3.x + f3.y * f3.y;
    }
#pragma unroll
    for (int o = 16; o; o >>= 1) s += __shfl_xor_sync(0xFFFFFFFFu, s, o);
    if (lid == 0) g_invcmn[j] = 1.0f / fmaxf(sqrtf(s), EPSV);
}

// ---------------- K5: fp16 mma.sync GEMM ----------------
// out[512,4096] = x_h @ Mth^T, norms folded in epilogue.
// BM=128, BN=128, BK=64 halfs; 8 warps (2m x 4n), warp tile 64x32, m16n8k16.
// 4-stage cp.async pipeline, 32KB/stage.
static constexpr int SMEM_DYN = 1024 + 4 * 32768;
static constexpr int NKT = 64;                 // k-tiles of 64

__global__ __launch_bounds__(256, 1)
void k_gemm_mma(float* __restrict__ out) {
    extern __shared__ char smraw[];
    uint32_t raw = s2u(smraw);
    uint32_t sb = (raw + 1023) & ~1023u;       // 1024-aligned base
    // stage st: A at sb + st*32768 (16KB), B at +16384

    int tid = threadIdx.x;
    int lane = tid & 31, wid = tid >> 5;
    int wm = (wid >> 2) * 64;                  // warp m offset (0,64)
    int wn = (wid & 3) * 32;                   // warp n offset (0..96)
    int bn0 = blockIdx.x * 128, bm0 = blockIdx.y * 128;

    // ldmatrix per-lane addressing
    int q = lane >> 3, rr = lane & 7;
    uint32_t qk = (uint32_t)(q >> 1) * 16;     // +16B for high-k quads
    uint32_t xr = (uint32_t)(rr << 4);         // swizzle XOR
    int aRowL = wm + (q & 1) * 8 + rr;
    int bRowL = wn + (q & 1) * 8 + rr;

    float acc[4][4][4];
#pragma unroll
    for (int mt = 0; mt < 4; mt++)
#pragma unroll
        for (int n8 = 0; n8 < 4; n8++)
#pragma unroll
            for (int c = 0; c < 4; c++) acc[mt][n8][c] = 0.f;

    // per-thread load mapping: 4 chunks A + 4 chunks B, 16B each
    int lr = tid >> 1;                          // base row pair
    // simpler: fid = tid + 256*i, r = fid>>3 (0..127), c = fid&7 (0..7)
#define LOADSTAGE(st, t)                                                          \
    {                                                                             \
        size_t k0 = (size_t)(t) * 64;                                             \
        uint32_t sa = sb + (uint32_t)(st) * 32768u;                               \
        _Pragma("unroll")                                                         \
        for (int i = 0; i < 4; i++) {                                             \
            int fid = tid + 256 * i;                                              \
            int r = fid >> 3, c = fid & 7;                                        \
            uint32_t so = SWZ((uint32_t)(r * 128 + c * 16));                      \
            cpasync16(sa + so, &g_Ah[(size_t)(bm0 + r) * N4K + k0 + c * 8]);      \
            cpasync16(sa + 16384u + so,                                           \
                      &g_Mth[(size_t)(bn0 + r) * N4K + k0 + c * 8]);              \
        }                                                                         \
    }
#define COMMIT() asm volatile("cp.async.commit_group;" ::: "memory")

    LOADSTAGE(0, 0); COMMIT();
    LOADSTAGE(1, 1); COMMIT();
    LOADSTAGE(2, 2); COMMIT();

    (void)lr;
    for (int t = 0; t < NKT; t++) {
        asm volatile("cp.async.wait_group 2;" ::: "memory");
        __syncthreads();
        if (t + 3 < NKT) { LOADSTAGE((t + 3) & 3, t + 3); }
        COMMIT();

        uint32_t sa = sb + (uint32_t)(t & 3) * 32768u;
        uint32_t sB = sa + 16384u;
#pragma unroll
        for (int ks = 0; ks < 4; ks++) {
            uint32_t kb = ((uint32_t)(ks * 32) + qk) ^ xr;
            uint32_t a[4][4], b[2][4];
#pragma unroll
            for (int mt = 0; mt < 4; mt++)
                ldsm4(a[mt][0], a[mt][1], a[mt][2], a[mt][3],
                      sa + (uint32_t)(aRowL + mt * 16) * 128 + kb);
#pragma unroll
            for (int nt = 0; nt < 2; nt++)
                ldsm4(b[nt][0], b[nt][1], b[nt][2], b[nt][3],
                      sB + (uint32_t)(bRowL + nt * 16) * 128 + kb);
#pragma unroll
            for (int mt = 0; mt < 4; mt++)
#pragma unroll
                for (int n8 = 0; n8 < 4; n8++)
                    mma_f16(acc[mt][n8][0], acc[mt][n8][1], acc[mt][n8][2], acc[mt][n8][3],
                            a[mt][0], a[mt][1], a[mt][2], a[mt][3],
                            b[n8 >> 1][n8 & 1], b[n8 >> 1][(n8 & 1) + 2]);
        }
    }

    // ---- epilogue: fold row + column norms, write fp32 ----
    int g4 = lane >> 2, t4 = lane & 3;
#pragma unroll
    for (int mt = 0; mt < 4; mt++) {
        int row0 = bm0 + wm + mt * 16 + g4;
        int row1 = row0 + 8;
        float ir0 = g_invrn[row0], ir1 = g_invrn[row1];
#pragma unroll
        for (int n8 = 0; n8 < 4; n8++) {
            int col = bn0 + wn + n8 * 8 + 2 * t4;
            float c0 = g_invcmn[col], c1 = g_invcmn[col + 1];
            float2 v0 = make_float2(acc[mt][n8][0] * ir0 * c0, acc[mt][n8][1] * ir0 * c1);
            float2 v1 = make_float2(acc[mt][n8][2] * ir1 * c0, acc[mt][n8][3] * ir1 * c1);
            *(float2*)&out[(size_t)row0 * N4K + col] = v0;
            *(float2*)&out[(size_t)row1 * N4K + col] = v1;
        }
    }
}

// ---------------- launch ----------------
extern "C" void kernel_launch(void* const* d_in, const int* in_sizes, int n_in,
                              void* d_out, int out_size) {
    const float* x   = (const float*)d_in[0];   // (512, 4096)
    const float* w   = (const float*)d_in[1];   // (4096, 4096)
    const float* qf  = (const float*)d_in[2];   // (4096, 4096)
    const int*   qit = (const int*)d_in[3];     // (4096,)
    const int*   it  = (const int*)d_in[4];     // scalar
    float* out = (float*)d_out;                 // (512, 4096) fp32

    cudaFuncSetAttribute(k_gemm_mma, cudaFuncAttributeMaxDynamicSharedMemorySize, SMEM_DYN);

    k_rownorm_xh<<<64, 256>>>(x);
    k_colsq_ql<<<dim3(16, 16), 256>>>(w, qit, it);
    k_build<<<dim3(64, 64), dim3(64, 4)>>>(w, qf);
    k_rowsq_mt<<<512, 256>>>();
    k_gemm_mma<<<dim3(32, 4), 256, SMEM_DYN>>>(out);
}